// round 16
// baseline (speedup 1.0000x reference)
#include <cuda_runtime.h>
#include <cuda_bf16.h>
#include <mma.h>
#include <math.h>
#include <stdint.h>

using namespace nvcuda;

// Shapes (fixed): U=256, D=5120, N=16, R=160
#define U_DIM 256
#define D_DIM 5120
#define N_DIM 16
#define R_DIM 160
#define NCOL  176   // 160 (t) + 16 (B)
#define NPADW 192   // padded combined-W cols (11 valid n16 tiles + 1 zero)

typedef unsigned long long ull;

// ---------------- scratch ----------------
#define S1_SPLITS 64
#define S1_KC     80      // K per split = 5 chunks of 16
#define S1_KK     16
#define S1_NCH    (S1_KC / S1_KK)   // 5
#define S1_M      64      // users per block

__device__ float g_partial[S1_SPLITS * U_DIM * NCOL];        // 11.5 MB
__device__ float g_tbuf[U_DIM * NCOL];                       // t | B
__device__ __align__(16) __nv_bfloat16 g_xh[U_DIM * D_DIM];  // 2.5 MB
__device__ __align__(16) __nv_bfloat16 g_xl[U_DIM * D_DIM];
__device__ __align__(16) __nv_bfloat16 g_wh[D_DIM * NPADW];  // 1.9 MB
__device__ __align__(16) __nv_bfloat16 g_wl[D_DIM * NPADW];

// ---------------- helpers ----------------
__device__ __forceinline__ ull pack2(float v) {
    ull r; asm("mov.b64 %0, {%1, %1};" : "=l"(r) : "f"(v)); return r;
}
__device__ __forceinline__ ull combine2(float lo, float hi) {
    ull r; asm("mov.b64 %0, {%1, %2};" : "=l"(r) : "f"(lo), "f"(hi)); return r;
}
__device__ __forceinline__ void fma2(ull& acc, ull a, ull b) {
    asm("fma.rn.f32x2 %0, %1, %2, %0;" : "+l"(acc) : "l"(a), "l"(b));
}
__device__ __forceinline__ void lds_v2b64(ull& a, ull& b, uint32_t addr) {
    asm volatile("ld.shared.v2.b64 {%0, %1}, [%2];" : "=l"(a), "=l"(b) : "r"(addr));
}
__device__ __forceinline__ void cp16(uint32_t dst, const void* src) {
    asm volatile("cp.async.ca.shared.global [%0], [%1], 16;" :: "r"(dst), "l"(src));
}
__device__ __forceinline__ void cp_commit() { asm volatile("cp.async.commit_group;"); }
__device__ __forceinline__ void cp_wait0()  { asm volatile("cp.async.wait_group 0;"); }
__device__ __forceinline__ void cp_wait1()  { asm volatile("cp.async.wait_group 1;"); }

// ================= Stage 0: fp32 -> bf16 hi/lo conversion =======================
// x groups: 327680 (f4), w groups: 245760 (f4 of padded [5120,192])
#define XG (U_DIM * D_DIM / 4)         // 327680
#define WG (D_DIM * NPADW / 4)         // 245760
#define CV_BLOCKS ((XG + WG) / 256)    // 2240

__global__ void __launch_bounds__(256) convert_kernel(
    const float* __restrict__ x,
    const float* __restrict__ W1,   // [5120,160]
    const float* __restrict__ Bp)   // [5120,16]
{
    const int gidx = blockIdx.x * 256 + threadIdx.x;
    float4 v;
    uint2* dh;
    uint2* dl;
    if (gidx < XG) {
        v = ((const float4*)x)[gidx];
        dh = (uint2*)g_xh + gidx;
        dl = (uint2*)g_xl + gidx;
    } else {
        const int j = gidx - XG;
        const int k = j / (NPADW / 4);
        const int cg = j - k * (NPADW / 4);
        const int c = cg * 4;
        if (c < R_DIM) {
            v = *(const float4*)(W1 + (size_t)k * R_DIM + c);
        } else if (c < NCOL) {
            v = *(const float4*)(Bp + (size_t)k * N_DIM + (c - R_DIM));
        } else {
            v = make_float4(0.f, 0.f, 0.f, 0.f);
        }
        dh = (uint2*)g_wh + j;
        dl = (uint2*)g_wl + j;
    }
    __nv_bfloat162 h01 = __floats2bfloat162_rn(v.x, v.y);
    __nv_bfloat162 h23 = __floats2bfloat162_rn(v.z, v.w);
    float l0 = v.x - __bfloat162float(__low2bfloat16(h01));
    float l1 = v.y - __bfloat162float(__high2bfloat16(h01));
    float l2 = v.z - __bfloat162float(__low2bfloat16(h23));
    float l3 = v.w - __bfloat162float(__high2bfloat16(h23));
    __nv_bfloat162 l01 = __floats2bfloat162_rn(l0, l1);
    __nv_bfloat162 l23 = __floats2bfloat162_rn(l2, l3);
    uint2 ph, pl;
    ph.x = *(uint32_t*)&h01; ph.y = *(uint32_t*)&h23;
    pl.x = *(uint32_t*)&l01; pl.y = *(uint32_t*)&l23;
    *dh = ph;
    *dl = pl;
}

// ================= Stage 1: HMMA wmma GEMM (pure cp.async + mma) ================
// C[256,176] = x @ [W1|Bp]. grid (4 u-tiles, 64 k-splits) = 256 blocks, 8 warps.
// Per chunk k16: stage Ah/Al [64,16] + Bh/Bl [16,192] via cp.async (double buf).
__global__ void __launch_bounds__(256) stage1_wmma(void)
{
    __shared__ __align__(16) __nv_bfloat16 Ah[2][S1_M * S1_KK];    // 2x2KB
    __shared__ __align__(16) __nv_bfloat16 Al[2][S1_M * S1_KK];
    __shared__ __align__(16) __nv_bfloat16 Bh[2][S1_KK * NPADW];   // 2x6KB
    __shared__ __align__(16) __nv_bfloat16 Bl[2][S1_KK * NPADW];

    const int tid = threadIdx.x;
    const int wid = tid >> 5;
    const int u0  = blockIdx.x * S1_M;
    const int k0  = blockIdx.y * S1_KC;

    const uint32_t ah_b = (uint32_t)__cvta_generic_to_shared(Ah);
    const uint32_t al_b = (uint32_t)__cvta_generic_to_shared(Al);
    const uint32_t bh_b = (uint32_t)__cvta_generic_to_shared(Bh);
    const uint32_t bl_b = (uint32_t)__cvta_generic_to_shared(Bl);

    auto issue = [&](int s) {
        const int kb = k0 + s * S1_KK;
        const int b  = s & 1;
        // A: 64 rows x 32B (16 bf16) per matrix; 128 cp16 each -> 256 total
        {
            const int row = tid >> 1, half = tid & 1;     // tid<128 -> Ah else Al
            if (tid < 128) {
                cp16(ah_b + (uint32_t)(b * S1_M * S1_KK + row * S1_KK + half * 8) * 2u,
                     g_xh + (size_t)(u0 + row) * D_DIM + kb + half * 8);
            } else {
                const int r2 = (tid - 128) >> 1, h2 = tid & 1;
                cp16(al_b + (uint32_t)(b * S1_M * S1_KK + r2 * S1_KK + h2 * 8) * 2u,
                     g_xl + (size_t)(u0 + r2) * D_DIM + kb + h2 * 8);
            }
        }
        // B: 16 rows x 384B per matrix = 384 cp16 each
        for (int e = tid; e < 384; e += 256) {
            const int row = e / 24, seg = e - row * 24;
            cp16(bh_b + (uint32_t)(b * S1_KK * NPADW + row * NPADW + seg * 8) * 2u,
                 g_wh + (size_t)(kb + row) * NPADW + seg * 8);
        }
        for (int e = tid; e < 384; e += 256) {
            const int row = e / 24, seg = e - row * 24;
            cp16(bl_b + (uint32_t)(b * S1_KK * NPADW + row * NPADW + seg * 8) * 2u,
                 g_wl + (size_t)(kb + row) * NPADW + seg * 8);
        }
        cp_commit();
    };

    // warp tiles: m-row = wid>>1 (0..3); even warp n-tiles 0..5, odd 6..10
    const int mrow = wid >> 1;
    const int jt0  = (wid & 1) * 6;
    const int jcnt = (wid & 1) ? 5 : 6;

    wmma::fragment<wmma::accumulator, 16, 16, 16, float> cf[6];
#pragma unroll
    for (int j = 0; j < 6; ++j) wmma::fill_fragment(cf[j], 0.f);

    issue(0);

#pragma unroll 1
    for (int s = 0; s < S1_NCH; ++s) {
        const int b = s & 1;
        if (s + 1 < S1_NCH) { issue(s + 1); cp_wait1(); }
        else                { cp_wait0(); }
        __syncthreads();

        wmma::fragment<wmma::matrix_a, 16, 16, 16, __nv_bfloat16, wmma::row_major> ah, al;
        wmma::load_matrix_sync(ah, Ah[b] + mrow * 16 * S1_KK, S1_KK);
        wmma::load_matrix_sync(al, Al[b] + mrow * 16 * S1_KK, S1_KK);

#pragma unroll
        for (int j = 0; j < 6; ++j) {
            if (j < jcnt) {
                const int jt = jt0 + j;
                wmma::fragment<wmma::matrix_b, 16, 16, 16, __nv_bfloat16, wmma::row_major> bh, bl;
                wmma::load_matrix_sync(bh, Bh[b] + jt * 16, NPADW);
                wmma::load_matrix_sync(bl, Bl[b] + jt * 16, NPADW);
                wmma::mma_sync(cf[j], ah, bh, cf[j]);
                wmma::mma_sync(cf[j], al, bh, cf[j]);
                wmma::mma_sync(cf[j], ah, bl, cf[j]);
            }
        }
        __syncthreads();
    }

    float* pout = g_partial + (size_t)blockIdx.y * (U_DIM * NCOL)
                + (size_t)(u0 + mrow * 16) * NCOL;
#pragma unroll
    for (int j = 0; j < 6; ++j) {
        if (j < jcnt) {
            const int jt = jt0 + j;
            wmma::store_matrix_sync(pout + jt * 16, cf[j], NCOL, wmma::mem_row_major);
        }
    }
}

// ================= Stage 2: reduce 64 split partials (float4) ===================
#define RED_F4 (U_DIM * NCOL / 4)   // 11264
__global__ void __launch_bounds__(256) reduce_kernel() {
    const int idx = blockIdx.x * 256 + threadIdx.x;   // 44 * 256 == 11264
    const float4* p4 = (const float4*)g_partial;
    float4 s = make_float4(0.f, 0.f, 0.f, 0.f);
#pragma unroll 8
    for (int sp = 0; sp < S1_SPLITS; ++sp) {
        float4 v = __ldcg(p4 + (size_t)sp * RED_F4 + idx);
        s.x += v.x; s.y += v.y; s.z += v.z; s.w += v.w;
    }
    ((float4*)g_tbuf)[idx] = s;
}

// ================= Stage 3: fused dt-GEMM + softplus + streaming ================
// (exact R8 winner: FU_UT=8, RCH=16, 2-deep ping-pong, occ 6)
#define FU_UT 8
#define FU_DT 128
#define RCH 16
#define NCH (R_DIM / RCH)      // 10 chunks
#define W2CHUNK (RCH * FU_DT)  // 2048 floats

__global__ void __launch_bounds__(256, 6) fused_kernel(
    const float* __restrict__ W2,    // [160,5120]
    const float* __restrict__ bias,  // [5120]
    const float* __restrict__ x,     // [256,5120]
    const float4* __restrict__ abar4,
    const float4* __restrict__ hst4,
    float4* __restrict__ out4)
{
    __shared__ __align__(16) ull   tpair[R_DIM * 4];          // 5.1 KB
    __shared__ __align__(16) float w2sh[2 * W2CHUNK];         // 16 KB ping-pong
    __shared__ __align__(16) float c1sh[FU_UT * FU_DT];       // 4 KB
    __shared__ __align__(16) float Bsh[FU_UT * N_DIM];        // 0.5 KB

    const int u0  = blockIdx.x * FU_UT;
    const int d0  = blockIdx.y * FU_DT;
    const int tid = threadIdx.x;

    const uint32_t w2b = (uint32_t)__cvta_generic_to_shared(w2sh);
    const uint32_t tpb = (uint32_t)__cvta_generic_to_shared(tpair);

    {
#pragma unroll
        for (int q = 0; q < 2; ++q) {
            int ch = tid + q * 256;
            int row = ch >> 5, c = ch & 31;
            cp16(w2b + (uint32_t)(row * FU_DT + c * 4) * 4u,
                 W2 + (size_t)row * D_DIM + d0 + c * 4);
        }
    }
    cp_commit();

    for (int e = tid; e < R_DIM * 4; e += 256) {
        int r = e >> 2, p = e & 3;
        float lo = g_tbuf[(size_t)(u0 + 2 * p)     * NCOL + r];
        float hi = g_tbuf[(size_t)(u0 + 2 * p + 1) * NCOL + r];
        tpair[r * 4 + p] = combine2(lo, hi);
    }
    if (tid < FU_UT * N_DIM) {
        int u = tid >> 4, n = tid & 15;
        Bsh[tid] = g_tbuf[(size_t)(u0 + u) * NCOL + R_DIM + n];
    }

    const int dl = tid & 127;
    const int g  = tid >> 7;
    const int pg = g * 2;
    const int d  = d0 + dl;

    ull acc[2];
    acc[0] = 0ULL; acc[1] = 0ULL;

#pragma unroll 1
    for (int s = 0; s < NCH; ++s) {
        cp_wait0();
        __syncthreads();
        if (s + 1 < NCH) {
#pragma unroll
            for (int q = 0; q < 2; ++q) {
                int ch = tid + q * 256;
                int row = ch >> 5, c = ch & 31;
                cp16(w2b + (uint32_t)(((s + 1) & 1) * W2CHUNK + row * FU_DT + c * 4) * 4u,
                     W2 + (size_t)((s + 1) * RCH + row) * D_DIM + d0 + c * 4);
            }
            cp_commit();
        }
        const uint32_t wbase = w2b + (uint32_t)((s & 1) * W2CHUNK + dl) * 4u;
        const uint32_t tbase = tpb + (uint32_t)(s * RCH * 4 + pg) * 8u;
#pragma unroll
        for (int rr = 0; rr < RCH; ++rr) {
            float wv;
            asm volatile("ld.shared.b32 %0, [%1];"
                         : "=f"(wv) : "r"(wbase + (uint32_t)(rr * FU_DT) * 4u));
            const ull w2 = pack2(wv);
            ull p0, p1;
            lds_v2b64(p0, p1, tbase + (uint32_t)(rr * 4) * 8u);
            fma2(acc[0], p0, w2);
            fma2(acc[1], p1, w2);
        }
    }

    const float bz = bias[d];
    const int ug = g * 4;
#pragma unroll
    for (int i = 0; i < 2; ++i) {
        float z0, z1;
        asm("mov.b64 {%0, %1}, %2;" : "=f"(z0), "=f"(z1) : "l"(acc[i]));
        const int u = ug + 2 * i;
        z0 += bz; z1 += bz;
        const float dt0 = fmaxf(z0, 0.f) + log1pf(expf(-fabsf(z0)));
        const float dt1 = fmaxf(z1, 0.f) + log1pf(expf(-fabsf(z1)));
        c1sh[u * FU_DT + dl]       = dt0 * __ldg(x + (size_t)(u0 + u) * D_DIM + d);
        c1sh[(u + 1) * FU_DT + dl] = dt1 * __ldg(x + (size_t)(u0 + u + 1) * D_DIM + d);
    }
    __syncthreads();

    const int n4 = tid & 3;
    const int i0 = tid;
    const int i1 = tid + 256;

#pragma unroll 2
    for (int u = 0; u < FU_UT; ++u) {
        const size_t base = ((size_t)(u0 + u) * D_DIM + d0) * 4;
        const float4 b = *(const float4*)(Bsh + u * N_DIM + n4 * 4);
        const float c0 = c1sh[u * FU_DT + (i0 >> 2)];
        const float c1 = c1sh[u * FU_DT + (i1 >> 2)];

        const float4 a0 = __ldcs(abar4 + base + i0);
        const float4 h0 = __ldcs(hst4  + base + i0);
        const float4 a1 = __ldcs(abar4 + base + i1);
        const float4 h1 = __ldcs(hst4  + base + i1);

        float4 o0, o1;
        o0.x = fmaf(a0.x, h0.x, c0 * b.x);
        o0.y = fmaf(a0.y, h0.y, c0 * b.y);
        o0.z = fmaf(a0.z, h0.z, c0 * b.z);
        o0.w = fmaf(a0.w, h0.w, c0 * b.w);
        o1.x = fmaf(a1.x, h1.x, c1 * b.x);
        o1.y = fmaf(a1.y, h1.y, c1 * b.y);
        o1.z = fmaf(a1.z, h1.z, c1 * b.z);
        o1.w = fmaf(a1.w, h1.w, c1 * b.w);
        __stcs(out4 + base + i0, o0);
        __stcs(out4 + base + i1, o1);
    }
}

extern "C" void kernel_launch(void* const* d_in, const int* in_sizes, int n_in,
                              void* d_out, int out_size) {
    const float* x    = (const float*)d_in[0];   // [256,5120]
    const float* W1   = (const float*)d_in[1];   // [5120,160]
    const float* W2   = (const float*)d_in[2];   // [160,5120]
    const float* bias = (const float*)d_in[3];   // [5120]
    const float* Bp   = (const float*)d_in[4];   // [5120,16]
    const float* abar = (const float*)d_in[5];   // [256,5120,16]
    const float* hst  = (const float*)d_in[6];   // [256,5120,16]
    float* out = (float*)d_out;

    convert_kernel<<<CV_BLOCKS, 256>>>(x, W1, Bp);
    stage1_wmma<<<dim3(U_DIM / S1_M, S1_SPLITS), 256>>>();
    reduce_kernel<<<RED_F4 / 256, 256>>>();
    fused_kernel<<<dim3(U_DIM / FU_UT, D_DIM / FU_DT), 256>>>(
        W2, bias, x, (const float4*)abar, (const float4*)hst, (float4*)out);
}